// round 13
// baseline (speedup 1.0000x reference)
#include <cuda_runtime.h>
#include <cuda_bf16.h>
#include <cstdint>

#define BATCH 64
#define SEQ_T 1024
#define HID   1024
#define NTAG  64
#define BT    (BATCH * SEQ_T)          // 65536 rows
#define BTN   (BT * NTAG)              // 4194304 emission elems

#define TM 128                          // GEMM tile rows
#define TK 64
#define CHUNKS 8                        // 8 chunks of 128 t-steps per batch
#define NTILES (BT / TM)                // 512
#define NTHREADS 256
#define NGEMM 84                        // producer CTAs (SMs)
#define GRID (BATCH + NGEMM)            // 148 == SM count

// per-batch chunk-completion bitmask (bit c = chunk c of batch b written)
__device__ unsigned int g_flags[BATCH];

__global__ void reset_kernel() {
    if (threadIdx.x < BATCH) g_flags[threadIdx.x] = 0u;
}

// acquire load WITH memory clobber: nothing may be hoisted across this.
__device__ __forceinline__ unsigned ld_acq(const unsigned* p) {
    unsigned v;
    asm volatile("ld.acquire.gpu.global.u32 %0, [%1];"
                 : "=r"(v) : "l"(p) : "memory");
    return v;
}

// ---------------------------------------------------------------------------
// GEMM producer role: persistent, 256 threads, loops tiles chunk-major
// (tile t -> batch t&63, chunk t>>6) so all chunk-0 tiles complete first.
// FFMA2 inner loop, k-order per output preserved (validated numerics).
// ---------------------------------------------------------------------------
__device__ void gemm_role(
    unsigned char* dsm, int lane0,
    const float* __restrict__ A, const float* __restrict__ W,
    const float* __restrict__ bias, float* __restrict__ C)
{
    float* sA = (float*)dsm;             // [TK][TM]  32KB
    float* sW = sA + TK * TM;            // [TK][NTAG] 16KB

    const int tid = threadIdx.x;
    const int tx  = tid & 7;             // 8 cols of 8
    const int ty  = tid >> 3;            // 0..31 -> 4 rows each

    float bc[8];
#pragma unroll
    for (int c = 0; c < 8; c++) bc[c] = bias[tx * 8 + c];

    for (int tile = lane0; tile < NTILES; tile += NGEMM) {
        const int bb = tile & 63;
        const int cc = tile >> 6;
        const int m0 = (bb * CHUNKS + cc) * TM;

        unsigned long long acc[2][8];
#pragma unroll
        for (int r = 0; r < 2; r++)
#pragma unroll
            for (int c = 0; c < 8; c++) acc[r][c] = 0ull;

        for (int k0 = 0; k0 < HID; k0 += TK) {
            // A slab: 128 rows x 16 float4-chunks = 2048, 8 per thread
#pragma unroll
            for (int p = 0; p < 8; p++) {
                const int idx = p * NTHREADS + tid;
                const int row = idx >> 4;
                const int cq  = idx & 15;
                float4 v = *(const float4*)&A[(size_t)(m0 + row) * HID + k0 + cq * 4];
                sA[(cq * 4 + 0) * TM + row] = v.x;
                sA[(cq * 4 + 1) * TM + row] = v.y;
                sA[(cq * 4 + 2) * TM + row] = v.z;
                sA[(cq * 4 + 3) * TM + row] = v.w;
            }
            // W slab: 64 rows x 16 chunks = 1024, 4 per thread
#pragma unroll
            for (int p = 0; p < 4; p++) {
                const int idx = p * NTHREADS + tid;
                const int row = idx >> 4;
                const int cq  = idx & 15;
                float4 v = *(const float4*)&W[(size_t)row * HID + k0 + cq * 4];
                sW[(cq * 4 + 0) * NTAG + row] = v.x;
                sW[(cq * 4 + 1) * NTAG + row] = v.y;
                sW[(cq * 4 + 2) * NTAG + row] = v.z;
                sW[(cq * 4 + 3) * NTAG + row] = v.w;
            }
            __syncthreads();

#pragma unroll 8
            for (int kk = 0; kk < TK; kk++) {
                ulonglong2 a01 = *(const ulonglong2*)&sA[kk * TM + ty * 4];
                unsigned long long ap[2] = {a01.x, a01.y};

                float4 wA = *(const float4*)&sW[kk * NTAG + tx * 8];
                float4 wB = *(const float4*)&sW[kk * NTAG + tx * 8 + 4];
                float wv[8] = {wA.x, wA.y, wA.z, wA.w, wB.x, wB.y, wB.z, wB.w};

                unsigned long long wd[8];
#pragma unroll
                for (int c = 0; c < 8; c++)
                    asm("mov.b64 %0, {%1, %1};"
                        : "=l"(wd[c]) : "r"(__float_as_uint(wv[c])));

#pragma unroll
                for (int r = 0; r < 2; r++)
#pragma unroll
                    for (int c = 0; c < 8; c++)
                        asm("fma.rn.f32x2 %0, %1, %2, %0;"
                            : "+l"(acc[r][c]) : "l"(ap[r]), "l"(wd[c]));
            }
            __syncthreads();
        }

        // epilogue: 2 row-pairs x 8 cols
#pragma unroll
        for (int r = 0; r < 2; r++) {
            unsigned int lo[8], hi[8];
#pragma unroll
            for (int c = 0; c < 8; c++)
                asm("mov.b64 {%0, %1}, %2;"
                    : "=r"(lo[c]), "=r"(hi[c]) : "l"(acc[r][c]));
            const size_t base0 = (size_t)(m0 + ty * 4 + 2 * r)     * NTAG + tx * 8;
            const size_t base1 = (size_t)(m0 + ty * 4 + 2 * r + 1) * NTAG + tx * 8;
            float4 oa, ob;
            oa.x = __uint_as_float(lo[0]) + bc[0]; oa.y = __uint_as_float(lo[1]) + bc[1];
            oa.z = __uint_as_float(lo[2]) + bc[2]; oa.w = __uint_as_float(lo[3]) + bc[3];
            ob.x = __uint_as_float(lo[4]) + bc[4]; ob.y = __uint_as_float(lo[5]) + bc[5];
            ob.z = __uint_as_float(lo[6]) + bc[6]; ob.w = __uint_as_float(lo[7]) + bc[7];
            *(float4*)&C[base0] = oa; *(float4*)&C[base0 + 4] = ob;
            oa.x = __uint_as_float(hi[0]) + bc[0]; oa.y = __uint_as_float(hi[1]) + bc[1];
            oa.z = __uint_as_float(hi[2]) + bc[2]; oa.w = __uint_as_float(hi[3]) + bc[3];
            ob.x = __uint_as_float(hi[4]) + bc[4]; ob.y = __uint_as_float(hi[5]) + bc[5];
            ob.z = __uint_as_float(hi[6]) + bc[6]; ob.w = __uint_as_float(hi[7]) + bc[7];
            *(float4*)&C[base1] = oa; *(float4*)&C[base1 + 4] = ob;
        }

        __threadfence();
        __syncthreads();
        if (tid == 0) atomicOr(&g_flags[bb], 1u << cc);
    }
}

// ---------------------------------------------------------------------------
// Viterbi consumer (R4 step, validated) — alone on its SM.
// ---------------------------------------------------------------------------
__device__ __forceinline__ void vstep(
    const float* __restrict__ sc_in, float* __restrict__ sc_out,
    const float* tr, const float* __restrict__ tjfix,
    unsigned char* __restrict__ histrow, float e_cur, int j)
{
    const float4* sp = (const float4*)sc_in;
    float gm[16];
#pragma unroll
    for (int g = 0; g < 16; g++) {
        float4 s4 = sp[g];
        float c0 = s4.x + tr[4 * g + 0];
        float c1 = s4.y + tr[4 * g + 1];
        float c2 = s4.z + tr[4 * g + 2];
        float c3 = s4.w + tr[4 * g + 3];
        gm[g] = fmaxf(fmaxf(c0, c1), fmaxf(c2, c3));
    }
    float v1[8]; int b1[8];
#pragma unroll
    for (int k = 0; k < 8; k++) {
        bool p = gm[2 * k] >= gm[2 * k + 1];
        v1[k] = fmaxf(gm[2 * k], gm[2 * k + 1]);
        b1[k] = p ? 2 * k : 2 * k + 1;
    }
    float v2[4]; int b2[4];
#pragma unroll
    for (int k = 0; k < 4; k++) {
        bool p = v1[2 * k] >= v1[2 * k + 1];
        v2[k] = fmaxf(v1[2 * k], v1[2 * k + 1]);
        b2[k] = p ? b1[2 * k] : b1[2 * k + 1];
    }
    float v3[2]; int b3[2];
#pragma unroll
    for (int k = 0; k < 2; k++) {
        bool p = v2[2 * k] >= v2[2 * k + 1];
        v3[k] = fmaxf(v2[2 * k], v2[2 * k + 1]);
        b3[k] = p ? b2[2 * k] : b2[2 * k + 1];
    }
    bool pr = v3[0] >= v3[1];
    float best = fmaxf(v3[0], v3[1]);
    int gbase = (pr ? b3[0] : b3[1]) * 4;

    sc_out[j] = best + e_cur;          // EARLY STS: releases next step

    float f0 = sc_in[gbase + 0] + tjfix[gbase + 0];
    float f1 = sc_in[gbase + 1] + tjfix[gbase + 1];
    float f2 = sc_in[gbase + 2] + tjfix[gbase + 2];
    int idx = gbase + 3;
    if (f2 == best) idx = gbase + 2;
    if (f1 == best) idx = gbase + 1;
    if (f0 == best) idx = gbase + 0;
    histrow[j] = (unsigned char)idx;
}

__device__ __forceinline__ void spin_need(unsigned& have, unsigned need, int b) {
    if ((have & need) != need) {
        do {
            have = ld_acq(&g_flags[b]);
            if ((have & need) != need) __nanosleep(64);
        } while ((have & need) != need);
    }
}

__device__ void viterbi_role(
    unsigned char* dsm,
    const float* __restrict__ emission,
    const float* __restrict__ start_trans,
    const float* __restrict__ end_trans,
    const float* __restrict__ trans,
    float* __restrict__ tags_out,
    int write_tags)
{
    float* score  = (float*)dsm;                              // [2][NTAG]
    float* transT = (float*)(dsm + 2 * NTAG * 4);             // [NTAG][65]
    unsigned char* hist = dsm + 2 * NTAG * 4 + NTAG * 65 * 4; // [T][NTAG]

    const int b   = blockIdx.x;
    const int tid = threadIdx.x;     // 0..255; lanes 0..63 active
    const int j   = tid;
    const bool active = (tid < NTAG);

    float tr[64];
    if (active) {
#pragma unroll
        for (int i = 0; i < 64; i++) {
            tr[i] = trans[i * NTAG + j];
            transT[j * 65 + i] = tr[i];
        }
    }
    const float* tj = transT + j * 65;
    const float* eb = emission + (size_t)b * SEQ_T * NTAG;

    unsigned have = 0;
    spin_need(have, 1u, b);            // chunk 0 covers t = 0..127
    __syncthreads();

    if (active) score[j] = start_trans[j] + __ldcg(&eb[j]);
    __syncthreads();

    float ep[4];
    if (active) {
#pragma unroll
        for (int k = 0; k < 4; k++) ep[k] = __ldcg(&eb[(size_t)(1 + k) * NTAG + j]);
    }

    int cur = 0;
    for (int t = 1; t <= SEQ_T - 7; t += 4) {
        {   // this group prefetches emission up to t+7 (128-step chunks)
            int nc = (t + 7) >> 7;
            unsigned need = (nc >= 7) ? 0xffu : ((2u << nc) - 1u);
            spin_need(have, need, b);
        }
        float en[4];
        if (active) {
#pragma unroll
            for (int k = 0; k < 4; k++) {
                int tt = t + 4 + k;
                if (tt > SEQ_T - 1) tt = SEQ_T - 1;
                en[k] = __ldcg(&eb[(size_t)tt * NTAG + j]);
            }
        }
#pragma unroll
        for (int u = 0; u < 4; u++) {
            if (active)
                vstep(score + cur * NTAG, score + (cur ^ 1) * NTAG,
                      tr, tj, hist + (size_t)(t + u) * NTAG, ep[u], j);
            __syncthreads();
            cur ^= 1;
        }
        if (active) {
#pragma unroll
            for (int k = 0; k < 4; k++) ep[k] = en[k];
        }
    }
#pragma unroll
    for (int u = 0; u < 3; u++) {
        if (active)
            vstep(score + cur * NTAG, score + (cur ^ 1) * NTAG,
                  tr, tj, hist + (size_t)(SEQ_T - 3 + u) * NTAG, ep[u], j);
        __syncthreads();
        cur ^= 1;
    }

    if (active) score[cur * NTAG + j] += end_trans[j];
    __syncthreads();

    if (tid == 0 && write_tags) {
        float bestv = score[cur * NTAG];
        int bt = 0;
        for (int jj = 1; jj < NTAG; jj++) {
            float v = score[cur * NTAG + jj];
            if (v > bestv) { bestv = v; bt = jj; }
        }
        float* to = tags_out + (size_t)b * SEQ_T;
        int tag = bt;
        to[SEQ_T - 1] = (float)tag;
        for (int t = SEQ_T - 1; t >= 1; t--) {
            tag = hist[(size_t)t * NTAG + tag];
            to[t - 1] = (float)tag;
        }
    }
}

// ---------------------------------------------------------------------------
// SM-partitioned persistent kernel: 148 CTAs, 1 per SM (forced by 120KB smem
// request). Blocks 0..63 = viterbi (isolated SMs); 64..147 = persistent GEMM.
// ---------------------------------------------------------------------------
__global__ __launch_bounds__(NTHREADS) void fused_kernel(
    const float* __restrict__ A, const float* __restrict__ W,
    const float* __restrict__ bias,
    const float* __restrict__ start_trans,
    const float* __restrict__ end_trans,
    const float* __restrict__ trans,
    float* __restrict__ out, int write_tags)
{
    extern __shared__ unsigned char dsm[];
    if (blockIdx.x >= BATCH) {
        gemm_role(dsm, (int)blockIdx.x - BATCH, A, W, bias, out);
    } else {
        viterbi_role(dsm, out, start_trans, end_trans, trans, out + BTN, write_tags);
    }
}

// ---------------------------------------------------------------------------
// Host launcher
// ---------------------------------------------------------------------------
extern "C" void kernel_launch(void* const* d_in, const int* in_sizes, int n_in,
                              void* d_out, int out_size)
{
    const float* text        = (const float*)d_in[0];
    const float* W_em        = (const float*)d_in[2];
    const float* b_em        = (const float*)d_in[3];
    const float* start_trans = (const float*)d_in[4];
    const float* end_trans   = (const float*)d_in[5];
    const float* trans       = (const float*)d_in[6];
    float* out = (float*)d_out;

    // > half the SM smem carveout -> occupancy limit 1 CTA/SM.
    const int smem_bytes = 120000;
    static int configured = -1;
    if (configured < 0) {
        cudaFuncSetAttribute(fused_kernel,
                             cudaFuncAttributeMaxDynamicSharedMemorySize, smem_bytes);
        configured = 1;
    }
    const int write_tags = (out_size >= BTN + BT) ? 1 : 0;

    reset_kernel<<<1, BATCH>>>();
    fused_kernel<<<GRID, NTHREADS, smem_bytes>>>(
        text, W_em, b_em, start_trans, end_trans, trans, out, write_tags);
}

// round 14
// speedup vs baseline: 1.1996x; 1.1996x over previous
#include <cuda_runtime.h>
#include <cuda_bf16.h>
#include <cstdint>

#define BATCH 64
#define SEQ_T 1024
#define HID   1024
#define NTAG  64
#define BT    (BATCH * SEQ_T)          // 65536 rows
#define BTN   (BT * NTAG)              // 4194304 emission elems

#define TM 128                          // GEMM tile rows
#define TK 64
#define CHUNKS 8                        // 8 chunks of 128 t-steps per batch
#define NTILES (BT / TM)                // 512
#define NTHREADS 256
#define NGEMM 84                        // producer CTAs (SMs)
#define GRID (BATCH + NGEMM)            // 148 == SM count

// per-batch chunk-completion bitmask (bit c = chunk c of batch b written)
__device__ unsigned int g_flags[BATCH];

__global__ void reset_kernel() {
    if (threadIdx.x < BATCH) g_flags[threadIdx.x] = 0u;
}

// acquire load WITH memory clobber: nothing may be hoisted across this.
__device__ __forceinline__ unsigned ld_acq(const unsigned* p) {
    unsigned v;
    asm volatile("ld.acquire.gpu.global.u32 %0, [%1];"
                 : "=r"(v) : "l"(p) : "memory");
    return v;
}

// ---------------------------------------------------------------------------
// GEMM producer role: persistent, 256 threads, chunk-major tile loop.
// CONFLICT-FREE smem stores (consecutive lanes -> consecutive rows).
// Inner loop: acc[4 rows][4 colpairs]; W pairs load directly as ulonglong2
// (no packing movs), A duplicated via 4 movs. Per-output fp32 FMA order
// identical to all prior validated versions.
// ---------------------------------------------------------------------------
__device__ void gemm_role(
    unsigned char* dsm, int lane0,
    const float* __restrict__ A, const float* __restrict__ W,
    const float* __restrict__ bias, float* __restrict__ C)
{
    float* sA = (float*)dsm;             // [TK][TM]  32KB (k-major)
    float* sW = sA + TK * TM;            // [TK][NTAG] 16KB (k-major)

    const int tid = threadIdx.x;
    const int tx  = tid & 7;             // col group: 8 cols = 4 pairs
    const int ty  = tid >> 3;            // 0..31 -> rows ty*4 .. ty*4+3

    // loader mapping (conflict-free: consecutive tid -> consecutive row)
    const int arow = tid & 127;          // A row
    const int ahalf = tid >> 7;          // 0/1 -> k-chunks 0..7 / 8..15
    const int wrow = tid & 63;           // W row
    const int wgrp = tid >> 6;           // 0..3 -> k-chunks grp*4..+4

    float bc[8];
#pragma unroll
    for (int c = 0; c < 8; c++) bc[c] = bias[tx * 8 + c];

    for (int tile = lane0; tile < NTILES; tile += NGEMM) {
        const int bb = tile & 63;
        const int cc = tile >> 6;
        const int m0 = (bb * CHUNKS + cc) * TM;

        unsigned long long acc[4][4];
#pragma unroll
        for (int r = 0; r < 4; r++)
#pragma unroll
            for (int cp = 0; cp < 4; cp++) acc[r][cp] = 0ull;

        for (int k0 = 0; k0 < HID; k0 += TK) {
            // A slab: thread handles row `arow`, 8 float4 k-chunks
            {
                const float* ap = &A[(size_t)(m0 + arow) * HID + k0 + ahalf * 32];
#pragma unroll
                for (int q = 0; q < 8; q++) {
                    float4 v = *(const float4*)(ap + q * 4);
                    const int kq = ahalf * 8 + q;
                    sA[(kq * 4 + 0) * TM + arow] = v.x;
                    sA[(kq * 4 + 1) * TM + arow] = v.y;
                    sA[(kq * 4 + 2) * TM + arow] = v.z;
                    sA[(kq * 4 + 3) * TM + arow] = v.w;
                }
            }
            // W slab: thread handles row `wrow`, 4 float4 k-chunks
            {
                const float* wp = &W[(size_t)wrow * HID + k0 + wgrp * 16];
#pragma unroll
                for (int q = 0; q < 4; q++) {
                    float4 v = *(const float4*)(wp + q * 4);
                    const int kq = wgrp * 4 + q;
                    sW[(kq * 4 + 0) * NTAG + wrow] = v.x;
                    sW[(kq * 4 + 1) * NTAG + wrow] = v.y;
                    sW[(kq * 4 + 2) * NTAG + wrow] = v.z;
                    sW[(kq * 4 + 3) * NTAG + wrow] = v.w;
                }
            }
            __syncthreads();

#pragma unroll 8
            for (int kk = 0; kk < TK; kk++) {
                float4 av = *(const float4*)&sA[kk * TM + ty * 4];
                unsigned long long ad[4];
                asm("mov.b64 %0, {%1, %1};" : "=l"(ad[0]) : "r"(__float_as_uint(av.x)));
                asm("mov.b64 %0, {%1, %1};" : "=l"(ad[1]) : "r"(__float_as_uint(av.y)));
                asm("mov.b64 %0, {%1, %1};" : "=l"(ad[2]) : "r"(__float_as_uint(av.z)));
                asm("mov.b64 %0, {%1, %1};" : "=l"(ad[3]) : "r"(__float_as_uint(av.w)));

                ulonglong2 w01 = *(const ulonglong2*)&sW[kk * NTAG + tx * 8];
                ulonglong2 w23 = *(const ulonglong2*)&sW[kk * NTAG + tx * 8 + 4];
                unsigned long long wp4[4] = {w01.x, w01.y, w23.x, w23.y};

#pragma unroll
                for (int r = 0; r < 4; r++)
#pragma unroll
                    for (int cp = 0; cp < 4; cp++)
                        asm("fma.rn.f32x2 %0, %1, %2, %0;"
                            : "+l"(acc[r][cp]) : "l"(ad[r]), "l"(wp4[cp]));
            }
            __syncthreads();
        }

        // epilogue: 4 rows x 8 cols
#pragma unroll
        for (int r = 0; r < 4; r++) {
            float o[8];
#pragma unroll
            for (int cp = 0; cp < 4; cp++) {
                unsigned int lo, hi;
                asm("mov.b64 {%0, %1}, %2;" : "=r"(lo), "=r"(hi) : "l"(acc[r][cp]));
                o[2 * cp + 0] = __uint_as_float(lo) + bc[2 * cp + 0];
                o[2 * cp + 1] = __uint_as_float(hi) + bc[2 * cp + 1];
            }
            const size_t base = (size_t)(m0 + ty * 4 + r) * NTAG + tx * 8;
            *(float4*)&C[base]     = make_float4(o[0], o[1], o[2], o[3]);
            *(float4*)&C[base + 4] = make_float4(o[4], o[5], o[6], o[7]);
        }

        __threadfence();
        __syncthreads();
        if (tid == 0) atomicOr(&g_flags[bb], 1u << cc);
    }
}

// ---------------------------------------------------------------------------
// Viterbi consumer (R4 step, validated) — alone on its SM.
// ---------------------------------------------------------------------------
__device__ __forceinline__ void vstep(
    const float* __restrict__ sc_in, float* __restrict__ sc_out,
    const float* tr, const float* __restrict__ tjfix,
    unsigned char* __restrict__ histrow, float e_cur, int j)
{
    const float4* sp = (const float4*)sc_in;
    float gm[16];
#pragma unroll
    for (int g = 0; g < 16; g++) {
        float4 s4 = sp[g];
        float c0 = s4.x + tr[4 * g + 0];
        float c1 = s4.y + tr[4 * g + 1];
        float c2 = s4.z + tr[4 * g + 2];
        float c3 = s4.w + tr[4 * g + 3];
        gm[g] = fmaxf(fmaxf(c0, c1), fmaxf(c2, c3));
    }
    float v1[8]; int b1[8];
#pragma unroll
    for (int k = 0; k < 8; k++) {
        bool p = gm[2 * k] >= gm[2 * k + 1];
        v1[k] = fmaxf(gm[2 * k], gm[2 * k + 1]);
        b1[k] = p ? 2 * k : 2 * k + 1;
    }
    float v2[4]; int b2[4];
#pragma unroll
    for (int k = 0; k < 4; k++) {
        bool p = v1[2 * k] >= v1[2 * k + 1];
        v2[k] = fmaxf(v1[2 * k], v1[2 * k + 1]);
        b2[k] = p ? b1[2 * k] : b1[2 * k + 1];
    }
    float v3[2]; int b3[2];
#pragma unroll
    for (int k = 0; k < 2; k++) {
        bool p = v2[2 * k] >= v2[2 * k + 1];
        v3[k] = fmaxf(v2[2 * k], v2[2 * k + 1]);
        b3[k] = p ? b2[2 * k] : b2[2 * k + 1];
    }
    bool pr = v3[0] >= v3[1];
    float best = fmaxf(v3[0], v3[1]);
    int gbase = (pr ? b3[0] : b3[1]) * 4;

    sc_out[j] = best + e_cur;          // EARLY STS: releases next step

    float f0 = sc_in[gbase + 0] + tjfix[gbase + 0];
    float f1 = sc_in[gbase + 1] + tjfix[gbase + 1];
    float f2 = sc_in[gbase + 2] + tjfix[gbase + 2];
    int idx = gbase + 3;
    if (f2 == best) idx = gbase + 2;
    if (f1 == best) idx = gbase + 1;
    if (f0 == best) idx = gbase + 0;
    histrow[j] = (unsigned char)idx;
}

__device__ __forceinline__ void spin_need(unsigned& have, unsigned need, int b) {
    if ((have & need) != need) {
        do {
            have = ld_acq(&g_flags[b]);
            if ((have & need) != need) __nanosleep(64);
        } while ((have & need) != need);
    }
}

__device__ void viterbi_role(
    unsigned char* dsm,
    const float* __restrict__ emission,
    const float* __restrict__ start_trans,
    const float* __restrict__ end_trans,
    const float* __restrict__ trans,
    float* __restrict__ tags_out,
    int write_tags)
{
    float* score  = (float*)dsm;                              // [2][NTAG]
    float* transT = (float*)(dsm + 2 * NTAG * 4);             // [NTAG][65]
    unsigned char* hist = dsm + 2 * NTAG * 4 + NTAG * 65 * 4; // [T][NTAG]

    const int b   = blockIdx.x;
    const int tid = threadIdx.x;     // 0..255; lanes 0..63 active
    const int j   = tid;
    const bool active = (tid < NTAG);

    float tr[64];
    if (active) {
#pragma unroll
        for (int i = 0; i < 64; i++) {
            tr[i] = trans[i * NTAG + j];
            transT[j * 65 + i] = tr[i];
        }
    }
    const float* tj = transT + j * 65;
    const float* eb = emission + (size_t)b * SEQ_T * NTAG;

    unsigned have = 0;
    spin_need(have, 1u, b);            // chunk 0 covers t = 0..127
    __syncthreads();

    if (active) score[j] = start_trans[j] + __ldcg(&eb[j]);
    __syncthreads();

    float ep[4];
    if (active) {
#pragma unroll
        for (int k = 0; k < 4; k++) ep[k] = __ldcg(&eb[(size_t)(1 + k) * NTAG + j]);
    }

    int cur = 0;
    for (int t = 1; t <= SEQ_T - 7; t += 4) {
        {   // this group prefetches emission up to t+7 (128-step chunks)
            int nc = (t + 7) >> 7;
            unsigned need = (nc >= 7) ? 0xffu : ((2u << nc) - 1u);
            spin_need(have, need, b);
        }
        float en[4];
        if (active) {
#pragma unroll
            for (int k = 0; k < 4; k++) {
                int tt = t + 4 + k;
                if (tt > SEQ_T - 1) tt = SEQ_T - 1;
                en[k] = __ldcg(&eb[(size_t)tt * NTAG + j]);
            }
        }
#pragma unroll
        for (int u = 0; u < 4; u++) {
            if (active)
                vstep(score + cur * NTAG, score + (cur ^ 1) * NTAG,
                      tr, tj, hist + (size_t)(t + u) * NTAG, ep[u], j);
            __syncthreads();
            cur ^= 1;
        }
        if (active) {
#pragma unroll
            for (int k = 0; k < 4; k++) ep[k] = en[k];
        }
    }
#pragma unroll
    for (int u = 0; u < 3; u++) {
        if (active)
            vstep(score + cur * NTAG, score + (cur ^ 1) * NTAG,
                  tr, tj, hist + (size_t)(SEQ_T - 3 + u) * NTAG, ep[u], j);
        __syncthreads();
        cur ^= 1;
    }

    if (active) score[cur * NTAG + j] += end_trans[j];
    __syncthreads();

    if (tid == 0 && write_tags) {
        float bestv = score[cur * NTAG];
        int bt = 0;
        for (int jj = 1; jj < NTAG; jj++) {
            float v = score[cur * NTAG + jj];
            if (v > bestv) { bestv = v; bt = jj; }
        }
        float* to = tags_out + (size_t)b * SEQ_T;
        int tag = bt;
        to[SEQ_T - 1] = (float)tag;
        for (int t = SEQ_T - 1; t >= 1; t--) {
            tag = hist[(size_t)t * NTAG + tag];
            to[t - 1] = (float)tag;
        }
    }
}

// ---------------------------------------------------------------------------
// SM-partitioned persistent kernel: 148 CTAs, 1 per SM (forced by 120KB smem
// request). Blocks 0..63 = viterbi (isolated SMs); 64..147 = persistent GEMM.
// ---------------------------------------------------------------------------
__global__ __launch_bounds__(NTHREADS) void fused_kernel(
    const float* __restrict__ A, const float* __restrict__ W,
    const float* __restrict__ bias,
    const float* __restrict__ start_trans,
    const float* __restrict__ end_trans,
    const float* __restrict__ trans,
    float* __restrict__ out, int write_tags)
{
    extern __shared__ unsigned char dsm[];
    if (blockIdx.x >= BATCH) {
        gemm_role(dsm, (int)blockIdx.x - BATCH, A, W, bias, out);
    } else {
        viterbi_role(dsm, out, start_trans, end_trans, trans, out + BTN, write_tags);
    }
}

// ---------------------------------------------------------------------------
// Host launcher
// ---------------------------------------------------------------------------
extern "C" void kernel_launch(void* const* d_in, const int* in_sizes, int n_in,
                              void* d_out, int out_size)
{
    const float* text        = (const float*)d_in[0];
    const float* W_em        = (const float*)d_in[2];
    const float* b_em        = (const float*)d_in[3];
    const float* start_trans = (const float*)d_in[4];
    const float* end_trans   = (const float*)d_in[5];
    const float* trans       = (const float*)d_in[6];
    float* out = (float*)d_out;

    // > half the SM smem carveout -> occupancy limit 1 CTA/SM.
    const int smem_bytes = 120000;
    static int configured = -1;
    if (configured < 0) {
        cudaFuncSetAttribute(fused_kernel,
                             cudaFuncAttributeMaxDynamicSharedMemorySize, smem_bytes);
        configured = 1;
    }
    const int write_tags = (out_size >= BTN + BT) ? 1 : 0;

    reset_kernel<<<1, BATCH>>>();
    fused_kernel<<<GRID, NTHREADS, smem_bytes>>>(
        text, W_em, b_em, start_trans, end_trans, trans, out, write_tags);
}

// round 16
// speedup vs baseline: 2.0174x; 1.6817x over previous
#include <cuda_runtime.h>
#include <cuda_bf16.h>
#include <cstdint>

#define BATCH 64
#define SEQ_T 1024
#define HID   1024
#define NTAG  64
#define BT    (BATCH * SEQ_T)          // 65536 rows
#define BTN   (BT * NTAG)              // 4194304 emission elems

// ---------------------------------------------------------------------------
// Kernel 1: emission GEMM with packed f32x2 FMA (validated, ~150us as part
// of the 523us serial best). Unchanged.
// ---------------------------------------------------------------------------
#define TM 128
#define TK 64

__global__ __launch_bounds__(128) void emission_kernel(
    const float* __restrict__ A,
    const float* __restrict__ W,
    const float* __restrict__ bias,
    float* __restrict__ C)
{
    __shared__ float sA[TK][TM];
    __shared__ float sW[TK][NTAG];

    const int m0  = blockIdx.x * TM;
    const int tid = threadIdx.x;
    const int tx  = tid & 7;
    const int ty  = tid >> 3;

    unsigned long long acc[4][8];
#pragma unroll
    for (int r = 0; r < 4; r++)
#pragma unroll
        for (int c = 0; c < 8; c++) acc[r][c] = 0ull;

    for (int k0 = 0; k0 < HID; k0 += TK) {
        {
            const float* arow = &A[(size_t)(m0 + tid) * HID + k0];
#pragma unroll
            for (int q = 0; q < 16; q++) {
                float4 v = *(const float4*)(arow + q * 4);
                sA[q * 4 + 0][tid] = v.x;
                sA[q * 4 + 1][tid] = v.y;
                sA[q * 4 + 2][tid] = v.z;
                sA[q * 4 + 3][tid] = v.w;
            }
        }
        {
            const int wr = tid & 63;
            const int qh = (tid >> 6) * 8;
            const float* wrow = &W[(size_t)wr * HID + k0];
#pragma unroll
            for (int q = 0; q < 8; q++) {
                float4 v = *(const float4*)(wrow + (qh + q) * 4);
                sW[(qh + q) * 4 + 0][wr] = v.x;
                sW[(qh + q) * 4 + 1][wr] = v.y;
                sW[(qh + q) * 4 + 2][wr] = v.z;
                sW[(qh + q) * 4 + 3][wr] = v.w;
            }
        }
        __syncthreads();

#pragma unroll 8
        for (int kk = 0; kk < TK; kk++) {
            ulonglong2 a01 = *(const ulonglong2*)&sA[kk][ty * 8];
            ulonglong2 a23 = *(const ulonglong2*)&sA[kk][ty * 8 + 4];
            unsigned long long ap[4] = {a01.x, a01.y, a23.x, a23.y};

            float4 wA = *(const float4*)&sW[kk][tx * 8];
            float4 wB = *(const float4*)&sW[kk][tx * 8 + 4];
            float wv[8] = {wA.x, wA.y, wA.z, wA.w, wB.x, wB.y, wB.z, wB.w};

            unsigned long long wd[8];
#pragma unroll
            for (int c = 0; c < 8; c++)
                asm("mov.b64 %0, {%1, %1};" : "=l"(wd[c]) : "r"(__float_as_uint(wv[c])));

#pragma unroll
            for (int r = 0; r < 4; r++)
#pragma unroll
                for (int c = 0; c < 8; c++)
                    asm("fma.rn.f32x2 %0, %1, %2, %0;"
                        : "+l"(acc[r][c]) : "l"(ap[r]), "l"(wd[c]));
        }
        __syncthreads();
    }

    float bc[8];
#pragma unroll
    for (int c = 0; c < 8; c++) bc[c] = bias[tx * 8 + c];

#pragma unroll
    for (int r = 0; r < 4; r++) {
        unsigned int lo[8], hi[8];
#pragma unroll
        for (int c = 0; c < 8; c++)
            asm("mov.b64 {%0, %1}, %2;" : "=r"(lo[c]), "=r"(hi[c]) : "l"(acc[r][c]));
        const size_t base0 = (size_t)(m0 + ty * 8 + 2 * r)     * NTAG + tx * 8;
        const size_t base1 = (size_t)(m0 + ty * 8 + 2 * r + 1) * NTAG + tx * 8;
        float4 o0a, o0b, o1a, o1b;
        o0a.x = __uint_as_float(lo[0]) + bc[0]; o0a.y = __uint_as_float(lo[1]) + bc[1];
        o0a.z = __uint_as_float(lo[2]) + bc[2]; o0a.w = __uint_as_float(lo[3]) + bc[3];
        o0b.x = __uint_as_float(lo[4]) + bc[4]; o0b.y = __uint_as_float(lo[5]) + bc[5];
        o0b.z = __uint_as_float(lo[6]) + bc[6]; o0b.w = __uint_as_float(lo[7]) + bc[7];
        o1a.x = __uint_as_float(hi[0]) + bc[0]; o1a.y = __uint_as_float(hi[1]) + bc[1];
        o1a.z = __uint_as_float(hi[2]) + bc[2]; o1a.w = __uint_as_float(hi[3]) + bc[3];
        o1b.x = __uint_as_float(hi[4]) + bc[4]; o1b.y = __uint_as_float(hi[5]) + bc[5];
        o1b.z = __uint_as_float(hi[6]) + bc[6]; o1b.w = __uint_as_float(hi[7]) + bc[7];
        *(float4*)&C[base0]     = o0a;  *(float4*)&C[base0 + 4] = o0b;
        *(float4*)&C[base1]     = o1a;  *(float4*)&C[base1 + 4] = o1b;
    }
}

// ---------------------------------------------------------------------------
// Kernel 2: Viterbi, 64 CTAs x 64 threads (R4 structure, best measured).
// R13 micro-opts: packed add.rn.f32x2 candidates from ulonglong2 score loads
// against pre-packed trans pairs; cur eliminated (compile-time sc0/sc1
// addresses in the x4-unrolled bodies); running hist pointer.
// ---------------------------------------------------------------------------
__device__ __forceinline__ void vstep_p(
    const float* __restrict__ sc_in, float* __restrict__ sc_out,
    const unsigned long long* trp,     // 32 packed trans pairs (reg array)
    const float* __restrict__ tjfix,   // smem transT row for column j
    unsigned char* __restrict__ histrow,
    float e_cur, int j)
{
    const ulonglong2* sp = (const ulonglong2*)sc_in;
    float gm[16];
#pragma unroll
    for (int g = 0; g < 16; g++) {
        ulonglong2 s = sp[g];
        unsigned long long r0, r1;
        asm("add.rn.f32x2 %0, %1, %2;" : "=l"(r0) : "l"(s.x), "l"(trp[2 * g]));
        asm("add.rn.f32x2 %0, %1, %2;" : "=l"(r1) : "l"(s.y), "l"(trp[2 * g + 1]));
        float c0, c1, c2, c3;
        asm("mov.b64 {%0, %1}, %2;" : "=f"(c0), "=f"(c1) : "l"(r0));
        asm("mov.b64 {%0, %1}, %2;" : "=f"(c2), "=f"(c3) : "l"(r1));
        gm[g] = fmaxf(fmaxf(c0, c1), fmaxf(c2, c3));
    }
    // keep-left (first-occurrence) merge tree over 16 groups
    float v1[8]; int b1[8];
#pragma unroll
    for (int k = 0; k < 8; k++) {
        bool p = gm[2 * k] >= gm[2 * k + 1];
        v1[k] = fmaxf(gm[2 * k], gm[2 * k + 1]);
        b1[k] = p ? 2 * k : 2 * k + 1;
    }
    float v2[4]; int b2[4];
#pragma unroll
    for (int k = 0; k < 4; k++) {
        bool p = v1[2 * k] >= v1[2 * k + 1];
        v2[k] = fmaxf(v1[2 * k], v1[2 * k + 1]);
        b2[k] = p ? b1[2 * k] : b1[2 * k + 1];
    }
    float v3[2]; int b3[2];
#pragma unroll
    for (int k = 0; k < 2; k++) {
        bool p = v2[2 * k] >= v2[2 * k + 1];
        v3[k] = fmaxf(v2[2 * k], v2[2 * k + 1]);
        b3[k] = p ? b2[2 * k] : b2[2 * k + 1];
    }
    bool pr = v3[0] >= v3[1];
    float best = fmaxf(v3[0], v3[1]);
    int gbase = (pr ? b3[0] : b3[1]) * 4;

    sc_out[j] = best + e_cur;          // EARLY STS: releases next step

    // exact first-occurrence fixup in barrier shadow (bit-identical adds:
    // add.rn.f32x2 lane == scalar fadd.rn)
    float f0 = sc_in[gbase + 0] + tjfix[gbase + 0];
    float f1 = sc_in[gbase + 1] + tjfix[gbase + 1];
    float f2 = sc_in[gbase + 2] + tjfix[gbase + 2];
    int idx = gbase + 3;
    if (f2 == best) idx = gbase + 2;
    if (f1 == best) idx = gbase + 1;
    if (f0 == best) idx = gbase + 0;
    histrow[j] = (unsigned char)idx;
}

__global__ __launch_bounds__(64) void viterbi_kernel(
    const float* __restrict__ emission,     // [B, T, N]
    const float* __restrict__ start_trans,  // [N]
    const float* __restrict__ end_trans,    // [N]
    const float* __restrict__ trans,        // [N, N] row-major
    float* __restrict__ tags_out,           // [B, T] as float
    int write_tags)
{
    extern __shared__ unsigned char dsm[];
    float* sc0    = (float*)dsm;                              // buffer 0
    float* sc1    = sc0 + NTAG;                               // buffer 1
    float* transT = (float*)(dsm + 2 * NTAG * 4);             // [NTAG][65]
    unsigned char* hist = dsm + 2 * NTAG * 4 + NTAG * 65 * 4; // [T][NTAG]

    const int b = blockIdx.x;
    const int j = threadIdx.x;   // 0..63

    // trans column j: 32 packed pairs in registers + smem copy for fixup
    unsigned long long trp[32];
#pragma unroll
    for (int k = 0; k < 32; k++) {
        float t0 = trans[(2 * k)     * NTAG + j];
        float t1 = trans[(2 * k + 1) * NTAG + j];
        asm("mov.b64 %0, {%1, %2};" : "=l"(trp[k]) : "f"(t0), "f"(t1));
        transT[j * 65 + 2 * k]     = t0;
        transT[j * 65 + 2 * k + 1] = t1;
    }
    const float* tj = transT + j * 65;
    const float* eb = emission + (size_t)b * SEQ_T * NTAG;

    sc0[j] = start_trans[j] + eb[j];
    __syncthreads();

    // emission register pipeline, depth 4
    float ep[4];
#pragma unroll
    for (int k = 0; k < 4; k++) ep[k] = eb[(size_t)(1 + k) * NTAG + j];

    unsigned char* histp = hist + (size_t)1 * NTAG;   // row for t=1

    // main loop: t = 1,5,...,1017 (covers steps 1..1020); cur provably
    // returns to buffer 0 after each group of 4 -> hardcoded sc0/sc1.
    for (int t = 1; t <= SEQ_T - 7; t += 4) {
        float en[4];
#pragma unroll
        for (int k = 0; k < 4; k++) {
            int tt = t + 4 + k;
            if (tt > SEQ_T - 1) tt = SEQ_T - 1;
            en[k] = eb[(size_t)tt * NTAG + j];      // MLP=4, ~4 steps cover
        }
        vstep_p(sc0, sc1, trp, tj, histp, ep[0], j);  histp += NTAG;
        __syncthreads();
        vstep_p(sc1, sc0, trp, tj, histp, ep[1], j);  histp += NTAG;
        __syncthreads();
        vstep_p(sc0, sc1, trp, tj, histp, ep[2], j);  histp += NTAG;
        __syncthreads();
        vstep_p(sc1, sc0, trp, tj, histp, ep[3], j);  histp += NTAG;
        __syncthreads();
#pragma unroll
        for (int k = 0; k < 4; k++) ep[k] = en[k];
    }
    // remainder: steps 1021, 1022, 1023 — ends with scores in sc1
    vstep_p(sc0, sc1, trp, tj, histp, ep[0], j);  histp += NTAG;
    __syncthreads();
    vstep_p(sc1, sc0, trp, tj, histp, ep[1], j);  histp += NTAG;
    __syncthreads();
    vstep_p(sc0, sc1, trp, tj, histp, ep[2], j);
    __syncthreads();

    sc1[j] += end_trans[j];
    __syncthreads();

    if (j == 0 && write_tags) {
        float bestv = sc1[0];
        int bt = 0;
        for (int jj = 1; jj < NTAG; jj++) {
            float v = sc1[jj];
            if (v > bestv) { bestv = v; bt = jj; }
        }
        float* to = tags_out + (size_t)b * SEQ_T;
        int tag = bt;
        to[SEQ_T - 1] = (float)tag;
        for (int t = SEQ_T - 1; t >= 1; t--) {
            tag = hist[(size_t)t * NTAG + tag];
            to[t - 1] = (float)tag;
        }
    }
}

// ---------------------------------------------------------------------------
// Host launcher (serial: GEMM then viterbi — validated structure)
// ---------------------------------------------------------------------------
extern "C" void kernel_launch(void* const* d_in, const int* in_sizes, int n_in,
                              void* d_out, int out_size)
{
    const float* text        = (const float*)d_in[0];
    const float* W_em        = (const float*)d_in[2];
    const float* b_em        = (const float*)d_in[3];
    const float* start_trans = (const float*)d_in[4];
    const float* end_trans   = (const float*)d_in[5];
    const float* trans       = (const float*)d_in[6];
    float* out = (float*)d_out;

    emission_kernel<<<BT / TM, 128>>>(text, W_em, b_em, out);

    const int smem_bytes = 2 * NTAG * 4 + NTAG * 65 * 4 + SEQ_T * NTAG;
    cudaFuncSetAttribute(viterbi_kernel,
                         cudaFuncAttributeMaxDynamicSharedMemorySize, smem_bytes);
    const int write_tags = (out_size >= BTN + BT) ? 1 : 0;
    viterbi_kernel<<<BATCH, 64, smem_bytes>>>(
        out, start_trans, end_trans, trans, out + BTN, write_tags);
}

// round 17
// speedup vs baseline: 2.0643x; 1.0232x over previous
#include <cuda_runtime.h>
#include <cuda_bf16.h>
#include <cstdint>

#define BATCH 64
#define SEQ_T 1024
#define HID   1024
#define NTAG  64
#define BT    (BATCH * SEQ_T)          // 65536 rows
#define BTN   (BT * NTAG)              // 4194304 emission elems

// ---------------------------------------------------------------------------
// Kernel 1: emission GEMM with packed f32x2 FMA (validated). Unchanged.
// ---------------------------------------------------------------------------
#define TM 128
#define TK 64

__global__ __launch_bounds__(128) void emission_kernel(
    const float* __restrict__ A,
    const float* __restrict__ W,
    const float* __restrict__ bias,
    float* __restrict__ C)
{
    __shared__ float sA[TK][TM];
    __shared__ float sW[TK][NTAG];

    const int m0  = blockIdx.x * TM;
    const int tid = threadIdx.x;
    const int tx  = tid & 7;
    const int ty  = tid >> 3;

    unsigned long long acc[4][8];
#pragma unroll
    for (int r = 0; r < 4; r++)
#pragma unroll
        for (int c = 0; c < 8; c++) acc[r][c] = 0ull;

    for (int k0 = 0; k0 < HID; k0 += TK) {
        {
            const float* arow = &A[(size_t)(m0 + tid) * HID + k0];
#pragma unroll
            for (int q = 0; q < 16; q++) {
                float4 v = *(const float4*)(arow + q * 4);
                sA[q * 4 + 0][tid] = v.x;
                sA[q * 4 + 1][tid] = v.y;
                sA[q * 4 + 2][tid] = v.z;
                sA[q * 4 + 3][tid] = v.w;
            }
        }
        {
            const int wr = tid & 63;
            const int qh = (tid >> 6) * 8;
            const float* wrow = &W[(size_t)wr * HID + k0];
#pragma unroll
            for (int q = 0; q < 8; q++) {
                float4 v = *(const float4*)(wrow + (qh + q) * 4);
                sW[(qh + q) * 4 + 0][wr] = v.x;
                sW[(qh + q) * 4 + 1][wr] = v.y;
                sW[(qh + q) * 4 + 2][wr] = v.z;
                sW[(qh + q) * 4 + 3][wr] = v.w;
            }
        }
        __syncthreads();

#pragma unroll 8
        for (int kk = 0; kk < TK; kk++) {
            ulonglong2 a01 = *(const ulonglong2*)&sA[kk][ty * 8];
            ulonglong2 a23 = *(const ulonglong2*)&sA[kk][ty * 8 + 4];
            unsigned long long ap[4] = {a01.x, a01.y, a23.x, a23.y};

            float4 wA = *(const float4*)&sW[kk][tx * 8];
            float4 wB = *(const float4*)&sW[kk][tx * 8 + 4];
            float wv[8] = {wA.x, wA.y, wA.z, wA.w, wB.x, wB.y, wB.z, wB.w};

            unsigned long long wd[8];
#pragma unroll
            for (int c = 0; c < 8; c++)
                asm("mov.b64 %0, {%1, %1};" : "=l"(wd[c]) : "r"(__float_as_uint(wv[c])));

#pragma unroll
            for (int r = 0; r < 4; r++)
#pragma unroll
                for (int c = 0; c < 8; c++)
                    asm("fma.rn.f32x2 %0, %1, %2, %0;"
                        : "+l"(acc[r][c]) : "l"(ap[r]), "l"(wd[c]));
        }
        __syncthreads();
    }

    float bc[8];
#pragma unroll
    for (int c = 0; c < 8; c++) bc[c] = bias[tx * 8 + c];

#pragma unroll
    for (int r = 0; r < 4; r++) {
        unsigned int lo[8], hi[8];
#pragma unroll
        for (int c = 0; c < 8; c++)
            asm("mov.b64 {%0, %1}, %2;" : "=r"(lo[c]), "=r"(hi[c]) : "l"(acc[r][c]));
        const size_t base0 = (size_t)(m0 + ty * 8 + 2 * r)     * NTAG + tx * 8;
        const size_t base1 = (size_t)(m0 + ty * 8 + 2 * r + 1) * NTAG + tx * 8;
        float4 o0a, o0b, o1a, o1b;
        o0a.x = __uint_as_float(lo[0]) + bc[0]; o0a.y = __uint_as_float(lo[1]) + bc[1];
        o0a.z = __uint_as_float(lo[2]) + bc[2]; o0a.w = __uint_as_float(lo[3]) + bc[3];
        o0b.x = __uint_as_float(lo[4]) + bc[4]; o0b.y = __uint_as_float(lo[5]) + bc[5];
        o0b.z = __uint_as_float(lo[6]) + bc[6]; o0b.w = __uint_as_float(lo[7]) + bc[7];
        o1a.x = __uint_as_float(hi[0]) + bc[0]; o1a.y = __uint_as_float(hi[1]) + bc[1];
        o1a.z = __uint_as_float(hi[2]) + bc[2]; o1a.w = __uint_as_float(hi[3]) + bc[3];
        o1b.x = __uint_as_float(hi[4]) + bc[4]; o1b.y = __uint_as_float(hi[5]) + bc[5];
        o1b.z = __uint_as_float(hi[6]) + bc[6]; o1b.w = __uint_as_float(hi[7]) + bc[7];
        *(float4*)&C[base0]     = o0a;  *(float4*)&C[base0 + 4] = o0b;
        *(float4*)&C[base1]     = o1a;  *(float4*)&C[base1 + 4] = o1b;
    }
}

// ---------------------------------------------------------------------------
// Kernel 2: Viterbi, 64 CTAs x 64 threads. R15: triple-buffered scores with
// DEFERRED argmax fixup — step t's fixup executes in step t+1's body, where
// its gbase is already known, so the fixup LDS issues at body start and its
// latency hides under step t+1's compute. Critical path per step is now
// bar -> LDS -> packed adds/tree -> STS -> bar.
// ---------------------------------------------------------------------------
__device__ __forceinline__ void vstep_d(
    const float* __restrict__ sc_in, float* __restrict__ sc_out,
    const unsigned long long* trp,     // 32 packed trans pairs (regs)
    const float* __restrict__ tj,      // smem transT row for column j
    float e_cur, int j,
    unsigned char* __restrict__ my_hist,
    // deferred fixup state (rotated each call)
    const float*& p_in, float& p_best, int& p_gbase, unsigned char*& p_hist)
{
    // ---- deferred fixup for PREVIOUS step: loads can issue immediately ----
    float pf0 = p_in[p_gbase + 0] + tj[p_gbase + 0];
    float pf1 = p_in[p_gbase + 1] + tj[p_gbase + 1];
    float pf2 = p_in[p_gbase + 2] + tj[p_gbase + 2];

    // ---- this step's candidates + keep-left tree ----
    const ulonglong2* sp = (const ulonglong2*)sc_in;
    float gm[16];
#pragma unroll
    for (int g = 0; g < 16; g++) {
        ulonglong2 s = sp[g];
        unsigned long long r0, r1;
        asm("add.rn.f32x2 %0, %1, %2;" : "=l"(r0) : "l"(s.x), "l"(trp[2 * g]));
        asm("add.rn.f32x2 %0, %1, %2;" : "=l"(r1) : "l"(s.y), "l"(trp[2 * g + 1]));
        float c0, c1, c2, c3;
        asm("mov.b64 {%0, %1}, %2;" : "=f"(c0), "=f"(c1) : "l"(r0));
        asm("mov.b64 {%0, %1}, %2;" : "=f"(c2), "=f"(c3) : "l"(r1));
        gm[g] = fmaxf(fmaxf(c0, c1), fmaxf(c2, c3));
    }
    float v1[8]; int b1[8];
#pragma unroll
    for (int k = 0; k < 8; k++) {
        bool p = gm[2 * k] >= gm[2 * k + 1];
        v1[k] = fmaxf(gm[2 * k], gm[2 * k + 1]);
        b1[k] = p ? 2 * k : 2 * k + 1;
    }
    float v2[4]; int b2[4];
#pragma unroll
    for (int k = 0; k < 4; k++) {
        bool p = v1[2 * k] >= v1[2 * k + 1];
        v2[k] = fmaxf(v1[2 * k], v1[2 * k + 1]);
        b2[k] = p ? b1[2 * k] : b1[2 * k + 1];
    }
    float v3[2]; int b3[2];
#pragma unroll
    for (int k = 0; k < 2; k++) {
        bool p = v2[2 * k] >= v2[2 * k + 1];
        v3[k] = fmaxf(v2[2 * k], v2[2 * k + 1]);
        b3[k] = p ? b2[2 * k] : b2[2 * k + 1];
    }
    bool pr = v3[0] >= v3[1];
    float best = fmaxf(v3[0], v3[1]);
    int gbase = (pr ? b3[0] : b3[1]) * 4;

    sc_out[j] = best + e_cur;          // EARLY STS: releases next step

    // ---- finish deferred fixup (values loaded at body start) ----
    int pidx = p_gbase + 3;
    if (pf2 == p_best) pidx = p_gbase + 2;
    if (pf1 == p_best) pidx = p_gbase + 1;
    if (pf0 == p_best) pidx = p_gbase + 0;
    p_hist[j] = (unsigned char)pidx;

    // rotate deferred state to this step
    p_in = sc_in; p_best = best; p_gbase = gbase; p_hist = my_hist;
}

__global__ __launch_bounds__(64) void viterbi_kernel(
    const float* __restrict__ emission,     // [B, T, N]
    const float* __restrict__ start_trans,  // [N]
    const float* __restrict__ end_trans,    // [N]
    const float* __restrict__ trans,        // [N, N] row-major
    float* __restrict__ tags_out,           // [B, T] as float
    int write_tags)
{
    extern __shared__ unsigned char dsm[];
    float* sc0    = (float*)dsm;                              // [NTAG]
    float* sc1    = sc0 + NTAG;
    float* sc2    = sc1 + NTAG;
    float* transT = (float*)(dsm + 3 * NTAG * 4);             // [NTAG][65]
    unsigned char* hist = dsm + 3 * NTAG * 4 + NTAG * 65 * 4; // [T][NTAG]

    const int b = blockIdx.x;
    const int j = threadIdx.x;   // 0..63

    // trans column j: 32 packed pairs in registers + smem copy for fixup
    unsigned long long trp[32];
#pragma unroll
    for (int k = 0; k < 32; k++) {
        float t0 = trans[(2 * k)     * NTAG + j];
        float t1 = trans[(2 * k + 1) * NTAG + j];
        asm("mov.b64 %0, {%1, %2};" : "=l"(trp[k]) : "f"(t0), "f"(t1));
        transT[j * 65 + 2 * k]     = t0;
        transT[j * 65 + 2 * k + 1] = t1;
    }
    const float* tj = transT + j * 65;
    const float* eb = emission + (size_t)b * SEQ_T * NTAG;

    sc0[j] = start_trans[j] + eb[j];
    __syncthreads();

    // emission register pipeline, depth 3 (matches 3-step groups)
    float ep[3];
#pragma unroll
    for (int k = 0; k < 3; k++) ep[k] = eb[(size_t)(1 + k) * NTAG + j];

    // deferred-fixup state: dummy first entry targets unused hist row 0
    const float* p_in = sc0;
    float p_best = 0.0f;
    int p_gbase = 0;
    unsigned char* p_hist = hist;          // row 0 (never read)

    unsigned char* histp = hist + NTAG;    // row for t=1

    // 340 groups of 3: steps 1..1020 (rotation returns to sc0 each group)
    for (int g = 0; g < 340; g++) {
        const int t = 1 + 3 * g;
        float en[3];
#pragma unroll
        for (int k = 0; k < 3; k++) {
            int tt = t + 3 + k;
            if (tt > SEQ_T - 1) tt = SEQ_T - 1;
            en[k] = eb[(size_t)tt * NTAG + j];
        }
        vstep_d(sc0, sc1, trp, tj, ep[0], j, histp, p_in, p_best, p_gbase, p_hist); histp += NTAG;
        __syncthreads();
        vstep_d(sc1, sc2, trp, tj, ep[1], j, histp, p_in, p_best, p_gbase, p_hist); histp += NTAG;
        __syncthreads();
        vstep_d(sc2, sc0, trp, tj, ep[2], j, histp, p_in, p_best, p_gbase, p_hist); histp += NTAG;
        __syncthreads();
#pragma unroll
        for (int k = 0; k < 3; k++) ep[k] = en[k];
    }
    // remainder: steps 1021, 1022, 1023 — final scores land in sc0
    vstep_d(sc0, sc1, trp, tj, ep[0], j, histp, p_in, p_best, p_gbase, p_hist); histp += NTAG;
    __syncthreads();
    vstep_d(sc1, sc2, trp, tj, ep[1], j, histp, p_in, p_best, p_gbase, p_hist); histp += NTAG;
    __syncthreads();
    vstep_d(sc2, sc0, trp, tj, ep[2], j, histp, p_in, p_best, p_gbase, p_hist);
    __syncthreads();

    // final deferred fixup (t = 1023); p_in = sc2 is still intact
    {
        float f0 = p_in[p_gbase + 0] + tj[p_gbase + 0];
        float f1 = p_in[p_gbase + 1] + tj[p_gbase + 1];
        float f2 = p_in[p_gbase + 2] + tj[p_gbase + 2];
        int idx = p_gbase + 3;
        if (f2 == p_best) idx = p_gbase + 2;
        if (f1 == p_best) idx = p_gbase + 1;
        if (f0 == p_best) idx = p_gbase + 0;
        p_hist[j] = (unsigned char)idx;
    }

    sc0[j] += end_trans[j];
    __syncthreads();

    if (j == 0 && write_tags) {
        float bestv = sc0[0];
        int bt = 0;
        for (int jj = 1; jj < NTAG; jj++) {
            float v = sc0[jj];
            if (v > bestv) { bestv = v; bt = jj; }
        }
        float* to = tags_out + (size_t)b * SEQ_T;
        int tag = bt;
        to[SEQ_T - 1] = (float)tag;
        for (int t = SEQ_T - 1; t >= 1; t--) {
            tag = hist[(size_t)t * NTAG + tag];
            to[t - 1] = (float)tag;
        }
    }
}

// ---------------------------------------------------------------------------
// Host launcher (serial: GEMM then viterbi — validated structure)
// ---------------------------------------------------------------------------
extern "C" void kernel_launch(void* const* d_in, const int* in_sizes, int n_in,
                              void* d_out, int out_size)
{
    const float* text        = (const float*)d_in[0];
    const float* W_em        = (const float*)d_in[2];
    const float* b_em        = (const float*)d_in[3];
    const float* start_trans = (const float*)d_in[4];
    const float* end_trans   = (const float*)d_in[5];
    const float* trans       = (const float*)d_in[6];
    float* out = (float*)d_out;

    emission_kernel<<<BT / TM, 128>>>(text, W_em, b_em, out);

    const int smem_bytes = 3 * NTAG * 4 + NTAG * 65 * 4 + SEQ_T * NTAG;
    cudaFuncSetAttribute(viterbi_kernel,
                         cudaFuncAttributeMaxDynamicSharedMemorySize, smem_bytes);
    const int write_tags = (out_size >= BTN + BT) ? 1 : 0;
    viterbi_kernel<<<BATCH, 64, smem_bytes>>>(
        out, start_trans, end_trans, trans, out + BTN, write_tags);
}